// round 8
// baseline (speedup 1.0000x reference)
#include <cuda_runtime.h>
#include <cuda_fp16.h>
#include <mma.h>
#include <math.h>

using namespace nvcuda;

#define NN 50000
#define EE 400000
#define GG 64
#define FIN 16
#define HID 128
#define HEADS 4
#define C1 512   // HEADS*HID

#define SCAN_NB 196          // ceil(50000/256)
#define SCAN_PAD (SCAN_NB*256)

// ---------------- scratch (static device memory; no allocs) ----------------
__device__ __half   g_zh[NN * 64];        // aggregated x per head (fp16)  6.4 MB
__device__ __half   g_h2h[NN * HID];      // fp16                12.8 MB
__device__ __half   g_w1h[FIN * C1];      // W1 fp16
__device__ __half   g_w2h[C1 * HID];      // W2 fp16
__device__ float    g_as1[NN * HEADS], g_ad1[NN * HEADS];
__device__ float    g_as2[NN], g_ad2[NN];
__device__ float    g_pool[GG * HID];
__device__ float    g_cnt[GG];
// CSR by destination
__device__ int      g_deg[SCAN_PAD];
__device__ int      g_off[SCAN_PAD + 1];
__device__ int      g_cur[NN];
__device__ int      g_part[SCAN_NB];
__device__ int      g_csr_src[EE];

// ---------------- helpers ----------------
__device__ __forceinline__ float leaky(float x) { return x > 0.f ? x : 0.2f * x; }
__device__ __forceinline__ float eluf(float x)  { return x > 0.f ? x : expm1f(x); }

__device__ __forceinline__ float4 h4_to_f4(uint2 u) {
    __half2 a = *(__half2*)&u.x, b = *(__half2*)&u.y;
    float2 fa = __half22float2(a), fb = __half22float2(b);
    return make_float4(fa.x, fa.y, fb.x, fb.y);
}
__device__ __forceinline__ uint2 f4_to_h4(float4 v) {
    __half2 a = __floats2half2_rn(v.x, v.y), b = __floats2half2_rn(v.z, v.w);
    uint2 u; u.x = *(unsigned*)&a; u.y = *(unsigned*)&b; return u;
}
__device__ __forceinline__ void red_add_v4(float* p, float a, float b, float c, float d) {
    asm volatile("red.global.add.v4.f32 [%0], {%1,%2,%3,%4};"
                 :: "l"(p), "f"(a), "f"(b), "f"(c), "f"(d) : "memory");
}

// ---------------- K0: fp16 weight conversion + zeroing (grid-stride tasks) -------
__global__ void k_prepw(const float* __restrict__ W1, const float* __restrict__ W2) {
    int i = blockIdx.x * blockDim.x + threadIdx.x;
    if (i < C1 * HID) g_w2h[i] = __float2half_rn(W2[i]);
    if (i < FIN * C1) g_w1h[i] = __float2half_rn(W1[i]);
    if (i < SCAN_PAD) g_deg[i] = 0;
    if (i < GG * HID) g_pool[i] = 0.f;
    if (i < GG) g_cnt[i] = 0.f;
}

// ---------------- K1: layer1 logits + edge histogram + graph counts -------------
// Per block: fold att vectors into W1 (redundant, cheap), then per-node logits,
// then grid-stride edge histogram.
__global__ void k_att1hist(const float* __restrict__ x, const float* __restrict__ W1,
                           const float* __restrict__ as1, const float* __restrict__ ad1,
                           const int* __restrict__ dst, const int* __restrict__ batch) {
    __shared__ float ws[FIN * HEADS], wd[FIN * HEADS];
    int t = threadIdx.x;
    if (t < 128) {
        int idx = t & 63;
        int k = idx >> 2, h = idx & 3;
        const float* av = (t < 64) ? as1 : ad1;
        float s = 0.f;
        for (int c = 0; c < HID; c++) s += W1[k * C1 + h * HID + c] * av[h * HID + c];
        if (t < 64) ws[idx] = s; else wd[idx] = s;
    }
    __syncthreads();
    int n = blockIdx.x * 256 + t;
    if (n < NN) {
        float xr[FIN];
        const float4* xp = (const float4*)(x + n * FIN);
#pragma unroll
        for (int i = 0; i < 4; i++) {
            float4 v = xp[i];
            xr[i * 4 + 0] = v.x; xr[i * 4 + 1] = v.y; xr[i * 4 + 2] = v.z; xr[i * 4 + 3] = v.w;
        }
#pragma unroll
        for (int h = 0; h < HEADS; h++) {
            float s = 0.f, d = 0.f;
#pragma unroll
            for (int k = 0; k < FIN; k++) { s += xr[k] * ws[k * 4 + h]; d += xr[k] * wd[k * 4 + h]; }
            g_as1[n * 4 + h] = s;
            g_ad1[n * 4 + h] = d;
        }
        atomicAdd(&g_cnt[batch[n]], 1.f);
    }
    // edge histogram (grid-stride)
    int stride = gridDim.x * 256;
    for (int e = blockIdx.x * 256 + t; e < EE; e += stride)
        atomicAdd(&g_deg[dst[e]], 1);
}

// ---------------- CSR scan ----------------
__global__ void k_scan_block(void) {
    __shared__ int s[256];
    int t = threadIdx.x;
    int i = blockIdx.x * 256 + t;
    int v = g_deg[i];
    s[t] = v;
    __syncthreads();
#pragma unroll
    for (int o = 1; o < 256; o <<= 1) {
        int x = (t >= o) ? s[t - o] : 0;
        __syncthreads();
        s[t] += x;
        __syncthreads();
    }
    g_off[i] = s[t] - v;
    if (t == 255) g_part[blockIdx.x] = s[255];
}

// fused top-scan + add: each block reduces partials below its index locally
__global__ void k_scan_add(void) {
    __shared__ int sred[256];
    int b = blockIdx.x, t = threadIdx.x;
    sred[t] = (t < b && t < SCAN_NB) ? g_part[t] : 0;
    __syncthreads();
#pragma unroll
    for (int o = 128; o > 0; o >>= 1) {
        if (t < o) sred[t] += sred[t + o];
        __syncthreads();
    }
    int pref = sred[0];
    int i = b * 256 + t;
    if (i > SCAN_PAD) return;
    if (i == SCAN_PAD) { g_off[i] = EE; return; }
    int p = g_off[i] + pref;
    g_off[i] = p;
    if (i < NN) g_cur[i] = p;
}

__global__ void k_fill(const int* __restrict__ src, const int* __restrict__ dst) {
    int e = blockIdx.x * blockDim.x + threadIdx.x;
    if (e >= EE) return;
    int d = dst[e];
    int p = atomicAdd(&g_cur[d], 1);
    g_csr_src[p] = src[e];
}

// ---------------- K3: layer1 single-pass softmax + x-space aggregation ----------
// Thread per (node, head). No max-subtraction (logits are O(1); exp fp32-safe).
__global__ void k_zagg(const float* __restrict__ x) {
    int tid = blockIdx.x * blockDim.x + threadIdx.x;
    int n = tid >> 2, h = tid & 3;
    if (n >= NN) return;
    int p0 = g_off[n], p1 = g_off[n + 1];
    float adn = g_ad1[n * 4 + h];
    float a = __expf(leaky(g_as1[n * 4 + h] + adn));   // self-loop
    float S = a;
    float z[16];
    const float4* xp = (const float4*)(x + n * FIN);
#pragma unroll
    for (int q = 0; q < 4; q++) {
        float4 v = xp[q];
        z[q * 4 + 0] = a * v.x; z[q * 4 + 1] = a * v.y;
        z[q * 4 + 2] = a * v.z; z[q * 4 + 3] = a * v.w;
    }
    for (int p = p0; p < p1; p++) {
        int s = g_csr_src[p];
        float av = __expf(leaky(g_as1[s * 4 + h] + adn));
        S += av;
        const float4* sp = (const float4*)(x + s * FIN);
#pragma unroll
        for (int q = 0; q < 4; q++) {
            float4 v = sp[q];
            z[q * 4 + 0] += av * v.x; z[q * 4 + 1] += av * v.y;
            z[q * 4 + 2] += av * v.z; z[q * 4 + 3] += av * v.w;
        }
    }
    float Sinv = 1.f / S;
    __half* zp = &g_zh[n * 64 + h * 16];
#pragma unroll
    for (int q = 0; q < 4; q++) {
        float4 v = make_float4(z[q * 4 + 0] * Sinv, z[q * 4 + 1] * Sinv,
                               z[q * 4 + 2] * Sinv, z[q * 4 + 3] * Sinv);
        *(uint2*)&zp[q * 4] = f4_to_h4(v);
    }
}

// ---------------- K8: fused layer1-transform + layer2 GEMM (WMMA, M=128) -------
#define F_LD 136
#define Z_LD 72
#define W1_LD 520
#define OFF_AS 0
#define OFF_BS 34816
#define OFF_ZS 69632
#define OFF_W1 88064
#define OFF_B1 104704
#define OFF_SA 106752
#define OFF_SD 107264
#define SMEM_TOT 107776

__global__ __launch_bounds__(512, 2) void k_fused2(
    const float* __restrict__ b1,
    const float* __restrict__ as2, const float* __restrict__ ad2) {
    extern __shared__ __align__(16) char smem[];
    __half* As  = (__half*)(smem + OFF_AS);
    float*  Cs  = (float*)(smem + OFF_AS);     // alias (epilogue only)
    __half* Bs  = (__half*)(smem + OFF_BS);
    __half* zs  = (__half*)(smem + OFF_ZS);
    __half* w1s = (__half*)(smem + OFF_W1);
    float*  sb1 = (float*)(smem + OFF_B1);
    float*  sa  = (float*)(smem + OFF_SA);
    float*  sd  = (float*)(smem + OFF_SD);

    int t = threadIdx.x;
    int wid = t >> 5, lane = t & 31;
    int wm = wid >> 1, wn = wid & 1;
    int row0 = blockIdx.x * 128;

    if (t < C1) sb1[t] = b1[t];
    if (t < HID) { sa[t] = as2[t]; sd[t] = ad2[t]; }
#pragma unroll
    for (int j = 0; j < 16; j++) {
        int idx = t + j * 512;
        int r = idx >> 9, c = idx & 511;
        w1s[r * W1_LD + c] = g_w1h[idx];
    }
    {
        uint2 zzero; zzero.x = 0u; zzero.y = 0u;
#pragma unroll
        for (int j = 0; j < 4; j++) {
            int idx = t + j * 512;
            int r = idx >> 4, q = idx & 15;
            int row = row0 + r;
            uint2 v = (row < NN) ? ((const uint2*)g_zh)[row * 16 + q] : zzero;
            *(uint2*)&zs[r * Z_LD + q * 4] = v;
        }
    }

    wmma::fragment<wmma::accumulator, 16, 16, 16, float> acc[4];
#pragma unroll
    for (int i = 0; i < 4; i++) wmma::fill_fragment(acc[i], 0.f);
    __syncthreads();

    for (int h = 0; h < 4; h++) {
        int kt = h * 128;
        {
            wmma::fragment<wmma::matrix_a, 16, 16, 16, __half, wmma::row_major> af;
            wmma::load_matrix_sync(af, &zs[wm * 16 * Z_LD + h * 16], Z_LD);
#pragma unroll
            for (int nf = 0; nf < 4; nf++) {
                wmma::fragment<wmma::accumulator, 16, 16, 16, __half> acc2;
                wmma::fill_fragment(acc2, __float2half(0.f));
                wmma::fragment<wmma::matrix_b, 16, 16, 16, __half, wmma::row_major> bf;
                wmma::load_matrix_sync(bf, &w1s[kt + wn * 64 + nf * 16], W1_LD);
                wmma::mma_sync(acc2, af, bf, acc2);
                wmma::store_matrix_sync(&As[wm * 16 * F_LD + wn * 64 + nf * 16], acc2,
                                        F_LD, wmma::mem_row_major);
            }
        }
#pragma unroll
        for (int j = 0; j < 8; j++) {
            int idx = t + j * 512;
            int r = idx >> 5, c4 = idx & 31;
            *(uint2*)&Bs[r * F_LD + c4 * 4] = ((const uint2*)g_w2h)[(kt + r) * 32 + c4];
        }
        __syncthreads();
#pragma unroll
        for (int j = 0; j < 32; j++) {
            int idx = t + j * 512;
            int r = idx >> 7, c = idx & 127;
            float v = __half2float(As[r * F_LD + c]) + sb1[kt + c];
            As[r * F_LD + c] = __float2half_rn(eluf(v));
        }
        __syncthreads();
#pragma unroll
        for (int kk = 0; kk < 8; kk++) {
            wmma::fragment<wmma::matrix_a, 16, 16, 16, __half, wmma::row_major> af;
            wmma::load_matrix_sync(af, &As[wm * 16 * F_LD + kk * 16], F_LD);
#pragma unroll
            for (int nf = 0; nf < 4; nf++) {
                wmma::fragment<wmma::matrix_b, 16, 16, 16, __half, wmma::row_major> bf;
                wmma::load_matrix_sync(bf, &Bs[kk * 16 * F_LD + wn * 64 + nf * 16], F_LD);
                wmma::mma_sync(acc[nf], af, bf, acc[nf]);
            }
        }
        __syncthreads();
    }
#pragma unroll
    for (int nf = 0; nf < 4; nf++)
        wmma::store_matrix_sync(&Cs[wm * 16 * F_LD + wn * 64 + nf * 16], acc[nf],
                                F_LD, wmma::mem_row_major);
    __syncthreads();
    {
        int r2 = t >> 2, seg = t & 3;
        int row = row0 + r2;
        if (row < NN) {
            uint2* dstp = (uint2*)&g_h2h[row * HID];
#pragma unroll
            for (int j = 0; j < 8; j++) {
                int c4 = seg * 8 + j;
                float4 v = make_float4(Cs[r2 * F_LD + c4 * 4 + 0], Cs[r2 * F_LD + c4 * 4 + 1],
                                       Cs[r2 * F_LD + c4 * 4 + 2], Cs[r2 * F_LD + c4 * 4 + 3]);
                dstp[c4] = f4_to_h4(v);
            }
        }
    }
#pragma unroll
    for (int i = 0; i < 8; i++) {
        int rI = wid * 8 + i;
        int row = row0 + rI;
        float s = 0.f, d = 0.f;
#pragma unroll
        for (int c = 0; c < 4; c++) {
            float v = Cs[rI * F_LD + lane + c * 32];
            s += v * sa[lane + c * 32];
            d += v * sd[lane + c * 32];
        }
#pragma unroll
        for (int o = 16; o > 0; o >>= 1) {
            s += __shfl_xor_sync(0xffffffffu, s, o);
            d += __shfl_xor_sync(0xffffffffu, d, o);
        }
        if (lane == 0 && row < NN) { g_as2[row] = s; g_ad2[row] = d; }
    }
}

// ---------------- K12: layer2 single-pass gather + fused mean-pool --------------
// Warp per node, 8 nodes/block. Unnormalized accumulate, scale at end, then
// elu(+b2) and red.add into g_pool[graph].
__global__ void k_agg2pool(const int* __restrict__ batch, const float* __restrict__ b2) {
    int t = threadIdx.x;
    int w = t >> 5, lane = t & 31;
    int n = blockIdx.x * 8 + w;
    if (n >= NN) return;
    int p0 = g_off[n], p1 = g_off[n + 1];
    float adn = g_ad2[n];
    float a = __expf(leaky(g_as2[n] + adn));
    float S = a;
    const uint2* h2p = (const uint2*)g_h2h;
    float4 v = h4_to_f4(h2p[n * 32 + lane]);
    float4 acc = make_float4(a * v.x, a * v.y, a * v.z, a * v.w);
    for (int p = p0; p < p1; p++) {
        int s = g_csr_src[p];
        float av = __expf(leaky(g_as2[s] + adn));
        S += av;
        float4 vv = h4_to_f4(h2p[s * 32 + lane]);
        acc.x += av * vv.x; acc.y += av * vv.y;
        acc.z += av * vv.z; acc.w += av * vv.w;
    }
    float Sinv = 1.f / S;
    float4 bb = *(const float4*)&b2[lane * 4];
    float y0 = eluf(acc.x * Sinv + bb.x);
    float y1 = eluf(acc.y * Sinv + bb.y);
    float y2 = eluf(acc.z * Sinv + bb.z);
    float y3 = eluf(acc.w * Sinv + bb.w);
    int g = batch[n];
    red_add_v4(&g_pool[g * HID + lane * 4], y0, y1, y2, y3);
}

// ---------------- K14: graph MLP + classifier ----------------
__global__ void k_final(const float* __restrict__ gfeat,
                        const float* __restrict__ Wg1, const float* __restrict__ bg1,
                        const float* __restrict__ Wg2, const float* __restrict__ bg2,
                        const float* __restrict__ Wc1, const float* __restrict__ bc1,
                        const float* __restrict__ Wc2, const float* __restrict__ bc2,
                        float* __restrict__ out) {
    int g = blockIdx.x;
    int t = threadIdx.x;
    __shared__ float z[HID + 32];
    __shared__ float hg[32];
    __shared__ float gfr[10];
    __shared__ float t1[128];
    if (t < 10) gfr[t] = gfeat[g * 10 + t];
    __syncthreads();
    if (t < 32) {
        float s = bg1[t];
#pragma unroll
        for (int k = 0; k < 10; k++) s += gfr[k] * Wg1[k * 32 + t];
        hg[t] = fmaxf(s, 0.f);
    }
    if (t < HID) {
        float inv = 1.f / fmaxf(g_cnt[g], 1.f);
        z[t] = g_pool[g * HID + t] * inv;
    }
    __syncthreads();
    if (t < 32) {
        float s = bg2[t];
#pragma unroll
        for (int k = 0; k < 32; k++) s += hg[k] * Wg2[k * 32 + t];
        z[HID + t] = s;
    }
    __syncthreads();
    if (t < 128) {
        float s = bc1[t];
        for (int k = 0; k < HID + 32; k++) s += z[k] * Wc1[k * 128 + t];
        t1[t] = fmaxf(s, 0.f);
    }
    __syncthreads();
    if (t < 6) {
        float s = bc2[t];
        for (int k = 0; k < 128; k++) s += t1[k] * Wc2[k * 6 + t];
        out[g * 6 + t] = s;
    }
}

// ---------------- launch ----------------
extern "C" void kernel_launch(void* const* d_in, const int* in_sizes, int n_in,
                              void* d_out, int out_size) {
    const float* x     = (const float*)d_in[0];
    const int*   ei    = (const int*)d_in[1];
    const int*   batch = (const int*)d_in[2];
    const float* gfeat = (const float*)d_in[3];
    const float* W1    = (const float*)d_in[4];
    const float* as1   = (const float*)d_in[5];
    const float* ad1   = (const float*)d_in[6];
    const float* b1    = (const float*)d_in[7];
    const float* W2    = (const float*)d_in[8];
    const float* as2   = (const float*)d_in[9];
    const float* ad2   = (const float*)d_in[10];
    const float* b2    = (const float*)d_in[11];
    const float* Wg1   = (const float*)d_in[12];
    const float* bg1   = (const float*)d_in[13];
    const float* Wg2   = (const float*)d_in[14];
    const float* bg2   = (const float*)d_in[15];
    const float* Wc1   = (const float*)d_in[16];
    const float* bc1   = (const float*)d_in[17];
    const float* Wc2   = (const float*)d_in[18];
    const float* bc2   = (const float*)d_in[19];
    float* out = (float*)d_out;

    const int* src = ei;
    const int* dst = ei + EE;

    cudaFuncSetAttribute(k_fused2, cudaFuncAttributeMaxDynamicSharedMemorySize, SMEM_TOT);

    k_prepw<<<(C1 * HID + 255) / 256, 256>>>(W1, W2);
    k_att1hist<<<196, 256>>>(x, W1, as1, ad1, dst, batch);
    k_scan_block<<<SCAN_NB, 256>>>();
    k_scan_add<<<SCAN_NB + 1, 256>>>();
    k_fill<<<(EE + 255) / 256, 256>>>(src, dst);
    k_zagg<<<(NN * 4 + 255) / 256, 256>>>(x);
    k_fused2<<<(NN + 127) / 128, 512, SMEM_TOT>>>(b1, as2, ad2);
    k_agg2pool<<<(NN + 7) / 8, 256>>>(batch, b2);
    k_final<<<GG, 160>>>(gfeat, Wg1, bg1, Wg2, bg2, Wc1, bc1, Wc2, bc2, out);
}

// round 9
// speedup vs baseline: 1.0375x; 1.0375x over previous
#include <cuda_runtime.h>
#include <cuda_fp16.h>
#include <mma.h>
#include <math.h>

using namespace nvcuda;

#define NN 50000
#define EE 400000
#define GG 64
#define FIN 16
#define HID 128
#define HEADS 4
#define C1 512   // HEADS*HID

#define SCAN_NB 196          // ceil(50000/256)
#define SCAN_PAD (SCAN_NB*256)

// ---------------- scratch (static device memory; no allocs) ----------------
__device__ __half   g_zh[NN * 64];        // aggregated x per head (fp16)  6.4 MB
__device__ __half   g_h2h[NN * HID];      // fp16                12.8 MB
__device__ __half   g_w1h[FIN * C1];      // W1 fp16
__device__ __half   g_w2h[C1 * HID];      // W2 fp16
__device__ float    g_as1[NN * HEADS], g_ad1[NN * HEADS];
__device__ float    g_as2[NN], g_ad2[NN];
__device__ float    g_pool[GG * HID];
__device__ float    g_cnt[GG];
// CSR by destination
__device__ int      g_deg[SCAN_PAD];
__device__ int      g_off[SCAN_PAD + 1];
__device__ int      g_cur[NN];
__device__ int      g_part[SCAN_NB];
__device__ int      g_csr_src[EE];

// ---------------- helpers ----------------
__device__ __forceinline__ float leaky(float x) { return x > 0.f ? x : 0.2f * x; }
__device__ __forceinline__ float eluf(float x)  { return x > 0.f ? x : expm1f(x); }

__device__ __forceinline__ float4 h4_to_f4(uint2 u) {
    __half2 a = *(__half2*)&u.x, b = *(__half2*)&u.y;
    float2 fa = __half22float2(a), fb = __half22float2(b);
    return make_float4(fa.x, fa.y, fb.x, fb.y);
}
__device__ __forceinline__ uint2 f4_to_h4(float4 v) {
    __half2 a = __floats2half2_rn(v.x, v.y), b = __floats2half2_rn(v.z, v.w);
    uint2 u; u.x = *(unsigned*)&a; u.y = *(unsigned*)&b; return u;
}
__device__ __forceinline__ void red_add_f32(float* p, float v) {
    asm volatile("red.global.add.f32 [%0], %1;" :: "l"(p), "f"(v) : "memory");
}

// ---------------- K0: fp16 weight conversion + zeroing (grid-stride tasks) -------
__global__ void k_prepw(const float* __restrict__ W1, const float* __restrict__ W2) {
    int i = blockIdx.x * blockDim.x + threadIdx.x;
    if (i < C1 * HID) g_w2h[i] = __float2half_rn(W2[i]);
    if (i < FIN * C1) g_w1h[i] = __float2half_rn(W1[i]);
    if (i < SCAN_PAD) g_deg[i] = 0;
    if (i < GG * HID) g_pool[i] = 0.f;
    if (i < GG) g_cnt[i] = 0.f;
}

// ---------------- K1: layer1 logits + edge histogram + graph counts -------------
__global__ void k_att1hist(const float* __restrict__ x, const float* __restrict__ W1,
                           const float* __restrict__ as1, const float* __restrict__ ad1,
                           const int* __restrict__ dst, const int* __restrict__ batch) {
    __shared__ float ws[FIN * HEADS], wd[FIN * HEADS];
    int t = threadIdx.x;
    if (t < 128) {
        int idx = t & 63;
        int k = idx >> 2, h = idx & 3;
        const float* av = (t < 64) ? as1 : ad1;
        float s = 0.f;
        for (int c = 0; c < HID; c++) s += W1[k * C1 + h * HID + c] * av[h * HID + c];
        if (t < 64) ws[idx] = s; else wd[idx] = s;
    }
    __syncthreads();
    int n = blockIdx.x * 256 + t;
    if (n < NN) {
        float xr[FIN];
        const float4* xp = (const float4*)(x + n * FIN);
#pragma unroll
        for (int i = 0; i < 4; i++) {
            float4 v = xp[i];
            xr[i * 4 + 0] = v.x; xr[i * 4 + 1] = v.y; xr[i * 4 + 2] = v.z; xr[i * 4 + 3] = v.w;
        }
#pragma unroll
        for (int h = 0; h < HEADS; h++) {
            float s = 0.f, d = 0.f;
#pragma unroll
            for (int k = 0; k < FIN; k++) { s += xr[k] * ws[k * 4 + h]; d += xr[k] * wd[k * 4 + h]; }
            g_as1[n * 4 + h] = s;
            g_ad1[n * 4 + h] = d;
        }
        atomicAdd(&g_cnt[batch[n]], 1.f);
    }
    int stride = gridDim.x * 256;
    for (int e = blockIdx.x * 256 + t; e < EE; e += stride)
        atomicAdd(&g_deg[dst[e]], 1);
}

// ---------------- CSR scan ----------------
__global__ void k_scan_block(void) {
    __shared__ int s[256];
    int t = threadIdx.x;
    int i = blockIdx.x * 256 + t;
    int v = g_deg[i];
    s[t] = v;
    __syncthreads();
#pragma unroll
    for (int o = 1; o < 256; o <<= 1) {
        int x = (t >= o) ? s[t - o] : 0;
        __syncthreads();
        s[t] += x;
        __syncthreads();
    }
    g_off[i] = s[t] - v;
    if (t == 255) g_part[blockIdx.x] = s[255];
}

__global__ void k_scan_add(void) {
    __shared__ int sred[256];
    int b = blockIdx.x, t = threadIdx.x;
    sred[t] = (t < b && t < SCAN_NB) ? g_part[t] : 0;
    __syncthreads();
#pragma unroll
    for (int o = 128; o > 0; o >>= 1) {
        if (t < o) sred[t] += sred[t + o];
        __syncthreads();
    }
    int pref = sred[0];
    int i = b * 256 + t;
    if (i > SCAN_PAD) return;
    if (i == SCAN_PAD) { g_off[i] = EE; return; }
    int p = g_off[i] + pref;
    g_off[i] = p;
    if (i < NN) g_cur[i] = p;
}

__global__ void k_fill(const int* __restrict__ src, const int* __restrict__ dst) {
    int e = blockIdx.x * blockDim.x + threadIdx.x;
    if (e >= EE) return;
    int d = dst[e];
    int p = atomicAdd(&g_cur[d], 1);
    g_csr_src[p] = src[e];
}

// ---------------- K3: layer1 single-pass softmax + x-space aggregation ----------
__global__ void k_zagg(const float* __restrict__ x) {
    int tid = blockIdx.x * blockDim.x + threadIdx.x;
    int n = tid >> 2, h = tid & 3;
    if (n >= NN) return;
    int p0 = g_off[n], p1 = g_off[n + 1];
    float adn = g_ad1[n * 4 + h];
    float a = __expf(leaky(g_as1[n * 4 + h] + adn));   // self-loop
    float S = a;
    float z[16];
    const float4* xp = (const float4*)(x + n * FIN);
#pragma unroll
    for (int q = 0; q < 4; q++) {
        float4 v = xp[q];
        z[q * 4 + 0] = a * v.x; z[q * 4 + 1] = a * v.y;
        z[q * 4 + 2] = a * v.z; z[q * 4 + 3] = a * v.w;
    }
    for (int p = p0; p < p1; p++) {
        int s = g_csr_src[p];
        float av = __expf(leaky(g_as1[s * 4 + h] + adn));
        S += av;
        const float4* sp = (const float4*)(x + s * FIN);
#pragma unroll
        for (int q = 0; q < 4; q++) {
            float4 v = sp[q];
            z[q * 4 + 0] += av * v.x; z[q * 4 + 1] += av * v.y;
            z[q * 4 + 2] += av * v.z; z[q * 4 + 3] += av * v.w;
        }
    }
    float Sinv = 1.f / S;
    __half* zp = &g_zh[n * 64 + h * 16];
#pragma unroll
    for (int q = 0; q < 4; q++) {
        float4 v = make_float4(z[q * 4 + 0] * Sinv, z[q * 4 + 1] * Sinv,
                               z[q * 4 + 2] * Sinv, z[q * 4 + 3] * Sinv);
        *(uint2*)&zp[q * 4] = f4_to_h4(v);
    }
}

// ---------------- K8: fused layer1-transform + layer2 GEMM (WMMA, M=128) -------
#define F_LD 136
#define Z_LD 72
#define W1_LD 520
#define OFF_AS 0
#define OFF_BS 34816
#define OFF_ZS 69632
#define OFF_W1 88064
#define OFF_B1 104704
#define OFF_SA 106752
#define OFF_SD 107264
#define SMEM_TOT 107776

__global__ __launch_bounds__(512) void k_fused2(
    const float* __restrict__ b1,
    const float* __restrict__ as2, const float* __restrict__ ad2) {
    extern __shared__ __align__(16) char smem[];
    __half* As  = (__half*)(smem + OFF_AS);
    float*  Cs  = (float*)(smem + OFF_AS);     // alias (epilogue only)
    __half* Bs  = (__half*)(smem + OFF_BS);
    __half* zs  = (__half*)(smem + OFF_ZS);
    __half* w1s = (__half*)(smem + OFF_W1);
    float*  sb1 = (float*)(smem + OFF_B1);
    float*  sa  = (float*)(smem + OFF_SA);
    float*  sd  = (float*)(smem + OFF_SD);

    int t = threadIdx.x;
    int wid = t >> 5, lane = t & 31;
    int wm = wid >> 1, wn = wid & 1;
    int row0 = blockIdx.x * 128;

    if (t < C1) sb1[t] = b1[t];
    if (t < HID) { sa[t] = as2[t]; sd[t] = ad2[t]; }
#pragma unroll
    for (int j = 0; j < 16; j++) {
        int idx = t + j * 512;
        int r = idx >> 9, c = idx & 511;
        w1s[r * W1_LD + c] = g_w1h[idx];
    }
    {
        uint2 zzero; zzero.x = 0u; zzero.y = 0u;
#pragma unroll
        for (int j = 0; j < 4; j++) {
            int idx = t + j * 512;
            int r = idx >> 4, q = idx & 15;
            int row = row0 + r;
            uint2 v = (row < NN) ? ((const uint2*)g_zh)[row * 16 + q] : zzero;
            *(uint2*)&zs[r * Z_LD + q * 4] = v;
        }
    }

    wmma::fragment<wmma::accumulator, 16, 16, 16, float> acc[4];
#pragma unroll
    for (int i = 0; i < 4; i++) wmma::fill_fragment(acc[i], 0.f);
    __syncthreads();

    for (int h = 0; h < 4; h++) {
        int kt = h * 128;
        {
            wmma::fragment<wmma::matrix_a, 16, 16, 16, __half, wmma::row_major> af;
            wmma::load_matrix_sync(af, &zs[wm * 16 * Z_LD + h * 16], Z_LD);
#pragma unroll
            for (int nf = 0; nf < 4; nf++) {
                wmma::fragment<wmma::accumulator, 16, 16, 16, __half> acc2;
                wmma::fill_fragment(acc2, __float2half(0.f));
                wmma::fragment<wmma::matrix_b, 16, 16, 16, __half, wmma::row_major> bf;
                wmma::load_matrix_sync(bf, &w1s[kt + wn * 64 + nf * 16], W1_LD);
                wmma::mma_sync(acc2, af, bf, acc2);
                wmma::store_matrix_sync(&As[wm * 16 * F_LD + wn * 64 + nf * 16], acc2,
                                        F_LD, wmma::mem_row_major);
            }
        }
#pragma unroll
        for (int j = 0; j < 8; j++) {
            int idx = t + j * 512;
            int r = idx >> 5, c4 = idx & 31;
            *(uint2*)&Bs[r * F_LD + c4 * 4] = ((const uint2*)g_w2h)[(kt + r) * 32 + c4];
        }
        __syncthreads();
#pragma unroll
        for (int j = 0; j < 32; j++) {
            int idx = t + j * 512;
            int r = idx >> 7, c = idx & 127;
            float v = __half2float(As[r * F_LD + c]) + sb1[kt + c];
            As[r * F_LD + c] = __float2half_rn(eluf(v));
        }
        __syncthreads();
#pragma unroll
        for (int kk = 0; kk < 8; kk++) {
            wmma::fragment<wmma::matrix_a, 16, 16, 16, __half, wmma::row_major> af;
            wmma::load_matrix_sync(af, &As[wm * 16 * F_LD + kk * 16], F_LD);
#pragma unroll
            for (int nf = 0; nf < 4; nf++) {
                wmma::fragment<wmma::matrix_b, 16, 16, 16, __half, wmma::row_major> bf;
                wmma::load_matrix_sync(bf, &Bs[kk * 16 * F_LD + wn * 64 + nf * 16], F_LD);
                wmma::mma_sync(acc[nf], af, bf, acc[nf]);
            }
        }
        __syncthreads();
    }
#pragma unroll
    for (int nf = 0; nf < 4; nf++)
        wmma::store_matrix_sync(&Cs[wm * 16 * F_LD + wn * 64 + nf * 16], acc[nf],
                                F_LD, wmma::mem_row_major);
    __syncthreads();
    {
        int r2 = t >> 2, seg = t & 3;
        int row = row0 + r2;
        if (row < NN) {
            uint2* dstp = (uint2*)&g_h2h[row * HID];
#pragma unroll
            for (int j = 0; j < 8; j++) {
                int c4 = seg * 8 + j;
                float4 v = make_float4(Cs[r2 * F_LD + c4 * 4 + 0], Cs[r2 * F_LD + c4 * 4 + 1],
                                       Cs[r2 * F_LD + c4 * 4 + 2], Cs[r2 * F_LD + c4 * 4 + 3]);
                dstp[c4] = f4_to_h4(v);
            }
        }
    }
#pragma unroll
    for (int i = 0; i < 8; i++) {
        int rI = wid * 8 + i;
        int row = row0 + rI;
        float s = 0.f, d = 0.f;
#pragma unroll
        for (int c = 0; c < 4; c++) {
            float v = Cs[rI * F_LD + lane + c * 32];
            s += v * sa[lane + c * 32];
            d += v * sd[lane + c * 32];
        }
#pragma unroll
        for (int o = 16; o > 0; o >>= 1) {
            s += __shfl_xor_sync(0xffffffffu, s, o);
            d += __shfl_xor_sync(0xffffffffu, d, o);
        }
        if (lane == 0 && row < NN) { g_as2[row] = s; g_ad2[row] = d; }
    }
}

// ---------------- K12: layer2 single-pass gather + block-reduced mean-pool ------
// Warp per node, 8 nodes/block. Rows parked in smem; 128 threads run-length
// accumulate over the 8 (batch-sorted) rows -> ~1-2 atomics per column per block.
__global__ void k_agg2pool(const int* __restrict__ batch, const float* __restrict__ b2) {
    __shared__ float sy[8][128];
    __shared__ int sg[8];
    int t = threadIdx.x;
    int w = t >> 5, lane = t & 31;
    int n = blockIdx.x * 8 + w;
    if (n < NN) {
        int p0 = g_off[n], p1 = g_off[n + 1];
        float adn = g_ad2[n];
        float a = __expf(leaky(g_as2[n] + adn));
        float S = a;
        const uint2* h2p = (const uint2*)g_h2h;
        float4 v = h4_to_f4(h2p[n * 32 + lane]);
        float4 acc = make_float4(a * v.x, a * v.y, a * v.z, a * v.w);
        for (int p = p0; p < p1; p++) {
            int s = g_csr_src[p];
            float av = __expf(leaky(g_as2[s] + adn));
            S += av;
            float4 vv = h4_to_f4(h2p[s * 32 + lane]);
            acc.x += av * vv.x; acc.y += av * vv.y;
            acc.z += av * vv.z; acc.w += av * vv.w;
        }
        float Sinv = 1.f / S;
        float4 bb = *(const float4*)&b2[lane * 4];
        float4 y = make_float4(eluf(acc.x * Sinv + bb.x), eluf(acc.y * Sinv + bb.y),
                               eluf(acc.z * Sinv + bb.z), eluf(acc.w * Sinv + bb.w));
        *(float4*)&sy[w][lane * 4] = y;
        if (lane == 0) sg[w] = batch[n];
    } else if (lane == 0) sg[w] = -1;
    __syncthreads();
    if (t < 128) {
        float acc = 0.f;
        int curg = -1;
#pragma unroll
        for (int r = 0; r < 8; r++) {
            int g = sg[r];
            if (g != curg) {
                if (curg >= 0) red_add_f32(&g_pool[curg * HID + t], acc);
                curg = g; acc = 0.f;
            }
            if (g >= 0) acc += sy[r][t];
        }
        if (curg >= 0) red_add_f32(&g_pool[curg * HID + t], acc);
    }
}

// ---------------- K14: graph MLP + classifier ----------------
__global__ void k_final(const float* __restrict__ gfeat,
                        const float* __restrict__ Wg1, const float* __restrict__ bg1,
                        const float* __restrict__ Wg2, const float* __restrict__ bg2,
                        const float* __restrict__ Wc1, const float* __restrict__ bc1,
                        const float* __restrict__ Wc2, const float* __restrict__ bc2,
                        float* __restrict__ out) {
    int g = blockIdx.x;
    int t = threadIdx.x;
    __shared__ float z[HID + 32];
    __shared__ float hg[32];
    __shared__ float gfr[10];
    __shared__ float t1[128];
    if (t < 10) gfr[t] = gfeat[g * 10 + t];
    __syncthreads();
    if (t < 32) {
        float s = bg1[t];
#pragma unroll
        for (int k = 0; k < 10; k++) s += gfr[k] * Wg1[k * 32 + t];
        hg[t] = fmaxf(s, 0.f);
    }
    if (t < HID) {
        float inv = 1.f / fmaxf(g_cnt[g], 1.f);
        z[t] = g_pool[g * HID + t] * inv;
    }
    __syncthreads();
    if (t < 32) {
        float s = bg2[t];
#pragma unroll
        for (int k = 0; k < 32; k++) s += hg[k] * Wg2[k * 32 + t];
        z[HID + t] = s;
    }
    __syncthreads();
    if (t < 128) {
        float s = bc1[t];
        for (int k = 0; k < HID + 32; k++) s += z[k] * Wc1[k * 128 + t];
        t1[t] = fmaxf(s, 0.f);
    }
    __syncthreads();
    if (t < 6) {
        float s = bc2[t];
        for (int k = 0; k < 128; k++) s += t1[k] * Wc2[k * 6 + t];
        out[g * 6 + t] = s;
    }
}

// ---------------- launch ----------------
extern "C" void kernel_launch(void* const* d_in, const int* in_sizes, int n_in,
                              void* d_out, int out_size) {
    const float* x     = (const float*)d_in[0];
    const int*   ei    = (const int*)d_in[1];
    const int*   batch = (const int*)d_in[2];
    const float* gfeat = (const float*)d_in[3];
    const float* W1    = (const float*)d_in[4];
    const float* as1   = (const float*)d_in[5];
    const float* ad1   = (const float*)d_in[6];
    const float* b1    = (const float*)d_in[7];
    const float* W2    = (const float*)d_in[8];
    const float* as2   = (const float*)d_in[9];
    const float* ad2   = (const float*)d_in[10];
    const float* b2    = (const float*)d_in[11];
    const float* Wg1   = (const float*)d_in[12];
    const float* bg1   = (const float*)d_in[13];
    const float* Wg2   = (const float*)d_in[14];
    const float* bg2   = (const float*)d_in[15];
    const float* Wc1   = (const float*)d_in[16];
    const float* bc1   = (const float*)d_in[17];
    const float* Wc2   = (const float*)d_in[18];
    const float* bc2   = (const float*)d_in[19];
    float* out = (float*)d_out;

    const int* src = ei;
    const int* dst = ei + EE;

    cudaFuncSetAttribute(k_fused2, cudaFuncAttributeMaxDynamicSharedMemorySize, SMEM_TOT);

    k_prepw<<<(C1 * HID + 255) / 256, 256>>>(W1, W2);
    k_att1hist<<<196, 256>>>(x, W1, as1, ad1, dst, batch);
    k_scan_block<<<SCAN_NB, 256>>>();
    k_scan_add<<<SCAN_NB + 1, 256>>>();
    k_fill<<<(EE + 255) / 256, 256>>>(src, dst);
    k_zagg<<<(NN * 4 + 255) / 256, 256>>>(x);
    k_fused2<<<(NN + 127) / 128, 512, SMEM_TOT>>>(b1, as2, ad2);
    k_agg2pool<<<(NN + 7) / 8, 256>>>(batch, b2);
    k_final<<<GG, 160>>>(gfeat, Wg1, bg1, Wg2, bg2, Wc1, bc1, Wc2, bc2, out);
}